// round 16
// baseline (speedup 1.0000x reference)
#include <cuda_runtime.h>

#define BB 64
#define HH 14
#define WWD 14
#define HW 196
#define CC 32
#define OO 10
#define NCH 7               // em hw-chunks per batch
#define HWB (HW/NCH)        // 28
#define TPB 320             // 10 warps: warp = o, lane = c
#define ACH 2               // mom chunks per batch
#define AHW (HW/ACH)        // 98
#define NWCH (ACH*16)       // 32 warp-chunks per batch
#define EPSF 1e-9f
#define LOG2PI 1.8378770664093453f

typedef unsigned long long u64;

// ---- f32x2 packed math (Blackwell) ---------------------------------------
__device__ __forceinline__ u64 pack2(float lo, float hi) {
    u64 r; asm("mov.b64 %0, {%1,%2};" : "=l"(r) : "f"(lo), "f"(hi)); return r;
}
__device__ __forceinline__ u64 pdup(float x) { return pack2(x, x); }
__device__ __forceinline__ void unpack2(u64 v, float& lo, float& hi) {
    asm("mov.b64 {%0,%1}, %2;" : "=f"(lo), "=f"(hi) : "l"(v));
}
__device__ __forceinline__ u64 fma2(u64 a, u64 b, u64 c) {
    u64 d; asm("fma.rn.f32x2 %0,%1,%2,%3;" : "=l"(d) : "l"(a), "l"(b), "l"(c)); return d;
}
__device__ __forceinline__ u64 mul2(u64 a, u64 b) {
    u64 d; asm("mul.rn.f32x2 %0,%1,%2;" : "=l"(d) : "l"(a), "l"(b)); return d;
}
__device__ __forceinline__ u64 add2(u64 a, u64 b) {
    u64 d; asm("add.rn.f32x2 %0,%1,%2;" : "=l"(d) : "l"(a), "l"(b)); return d;
}

// Scratch (fully rewritten every pass -> deterministic, graph-safe)
__device__ float g_partials[BB*NCH*OO*33];   // [b][chunk][o][S0,S1[16],S2[16]]
__device__ float g_params[BB*OO*33];         // [b][o][K, ivar[16], muinv[16]]
__device__ float g_mom[BB*NWCH*CC*70];       // mom warp-chunk partials
__device__ int   g_count[BB];                // em counters (winner resets)
__device__ int   g_cnt0[BB];                 // mom counters (winner resets)

// ===========================================================================
// PASS 0 via moments (rr = 1/O). grid=(ACH,BB), block=512 (16 warps).
// lane = c (coalesced LDG), warp = hw-strider over 98 positions.
// Each warp writes its 69 partial moments straight to g_mom (32 chunks/b);
// winner block sums chunks in smem and assembles routing params.
// Moment layout per c (69): [0]=sum a; [1..16]=sum a*p_j;
// [17+10i+idx(j<=k)]=sum a*p_{4i+j}p_{4i+k}; [57]aw [58]ah [59]aw2 [60]ah2;
// [61..64]=a*ow*p_{0..3}; [65..68]=a*oh*p_{4..7}.
// ===========================================================================
__global__ void __launch_bounds__(512)
caps_mom(const float* __restrict__ pose,
         const float* __restrict__ act,
         const float* __restrict__ w,
         const float* __restrict__ beta_a,
         const float* __restrict__ beta_u)
{
    __shared__ float mom[CC][70];   // winner combine buffer (35.8 KB)
    __shared__ int   s_win;

    const int ch  = blockIdx.x;     // 0..1
    const int b   = blockIdx.y;
    const int tid = threadIdx.x;
    const int wp  = tid >> 5;       // 0..15
    const int c   = tid & 31;

    float A[69];
    #pragma unroll
    for (int m = 0; m < 69; m++) A[m] = 0.f;

    for (int hwl = wp; hwl < AHW; hwl += 16) {
        const int hw = ch * AHW + hwl;
        const float4* pp = (const float4*)(pose + ((size_t)(b * HW + hw) * CC + c) * 16);
        float p[16];
        #pragma unroll
        for (int q = 0; q < 4; q++) {
            const float4 t4 = pp[q];
            p[q*4+0] = t4.x; p[q*4+1] = t4.y; p[q*4+2] = t4.z; p[q*4+3] = t4.w;
        }
        const float a = act[(size_t)(b * HW + hw) * CC + c];
        const int h    = hw / WWD;
        const int wpos = hw - h * WWD;
        const float ow = (wpos + 0.5f) * (1.0f / WWD);
        const float oh = (h    + 0.5f) * (1.0f / HH);

        float ap[16];
        #pragma unroll
        for (int j = 0; j < 16; j++) ap[j] = a * p[j];

        A[0] += a;
        #pragma unroll
        for (int j = 0; j < 16; j++) A[1 + j] += ap[j];
        #pragma unroll
        for (int i = 0; i < 4; i++) {
            const int mb = 17 + i * 10;
            const int pb = i * 4;
            int idx = 0;
            #pragma unroll
            for (int j = 0; j < 4; j++)
                #pragma unroll
                for (int k = j; k < 4; k++)
                    A[mb + (idx++)] += ap[pb + j] * p[pb + k];
        }
        const float aw = a * ow, ah = a * oh;
        A[57] += aw; A[58] += ah;
        A[59] += aw * ow; A[60] += ah * oh;
        #pragma unroll
        for (int j = 0; j < 4; j++) {
            A[61 + j] += aw * p[j];
            A[65 + j] += ah * p[4 + j];
        }
    }

    // ---- write warp-chunk partials straight to gmem ----------------------
    {
        float* dst = g_mom + (size_t)((b * NWCH + ch * 16 + wp) * CC + c) * 70;
        #pragma unroll
        for (int m = 0; m < 69; m++) dst[m] = A[m];
    }

    // ---- winner block per batch combines + assembles params --------------
    __threadfence();
    __syncthreads();
    if (tid == 0) {
        int prev = atomicAdd(&g_cnt0[b], 1);
        s_win = (prev == ACH - 1);
    }
    __syncthreads();
    if (!s_win) return;
    __threadfence();

    for (int idx = tid; idx < CC * 69; idx += 512) {
        const int cc = idx / 69;
        const int m  = idx - cc * 69;
        float s = 0.f;
        #pragma unroll 8
        for (int g = 0; g < NWCH; g++)
            s += g_mom[(size_t)((b * NWCH + g) * CC + cc) * 70 + m];
        mom[cc][m] = s;
    }
    __syncthreads();

    if (tid < OO * 16) {
        const int o   = tid >> 4;
        const int d   = tid & 15;
        const int i   = d >> 2;
        const int col = d & 3;

        float R0 = 0.f, S1 = 0.f, S2 = 0.f;
        for (int cc = 0; cc < CC; cc++) {
            const float* mc2 = mom[cc];
            const float* wc = w + ((size_t)(cc * OO + o) * 16) + col;
            const float w0 = wc[0], w1 = wc[4], w2 = wc[8], w3 = wc[12];
            R0 += mc2[0];
            const float* m1 = mc2 + 1 + i * 4;
            S1 += m1[0]*w0 + m1[1]*w1 + m1[2]*w2 + m1[3]*w3;
            const float* M = mc2 + 17 + i * 10;
            S2 += w0*w0*M[0] + w1*w1*M[4] + w2*w2*M[7] + w3*w3*M[9]
                + 2.f*(w0*w1*M[1] + w0*w2*M[2] + w0*w3*M[3]
                     + w1*w2*M[5] + w1*w3*M[6] + w2*w3*M[8]);
            if (d == 3) {
                S1 += mc2[57];
                S2 += mc2[59] + 2.f*(mc2[61]*w0 + mc2[62]*w1 + mc2[63]*w2 + mc2[64]*w3);
            }
            if (d == 7) {
                S1 += mc2[58];
                S2 += mc2[60] + 2.f*(mc2[65]*w0 + mc2[66]*w1 + mc2[67]*w2 + mc2[68]*w3);
            }
        }
        const float rs     = 0.1f * R0 + EPSF;
        const float inv_rs = 1.0f / rs;
        const float mu     = 0.1f * S1 * inv_rs;
        const float var    = fmaxf(0.1f * S2 * inv_rs - mu * mu, 0.0f) + EPSF;
        const float lv     = __logf(var);
        const float ivar   = 1.0f / var;
        const float muinv  = mu * ivar;
        const float mive   = mu * muinv;

        float sumlv = lv, summive = mive;
        #pragma unroll
        for (int off = 1; off < 16; off <<= 1) {
            sumlv   += __shfl_xor_sync(0xFFFFFFFFu, sumlv,   off);
            summive += __shfl_xor_sync(0xFFFFFFFFu, summive, off);
        }

        const float cost = rs * (16.0f * beta_u[o] + 0.5f * sumlv);
        const float actv = 1.0f / (1.0f + __expf(-(beta_a[o] - cost))); // inv_temp=1

        float* pp = g_params + (size_t)(b * OO + o) * 33;
        pp[1 + d]  = ivar;
        pp[17 + d] = muinv;
        if (d == 0)
            pp[0] = __logf(actv + EPSF)
                  - 0.5f * (16.0f * LOG2PI + sumlv)
                  - 0.5f * summive;
    }
    if (tid == 0) g_cnt0[b] = 0;
}

// ===========================================================================
// EM passes 1/2 (R14 verbatim): per-t softmax, HWB=28, grid (7,BB).
// ss/se packed at stride 12 -> max/den via float4+float2 loads.
// ===========================================================================
#define SMEM_EM (71680 + 1280 + 1536 + 1536 + 3584 + 64)

template<int FINAL>
__global__ void __launch_bounds__(TPB, 2)
caps_em(const float* __restrict__ pose,
        const float* __restrict__ act,
        const float* __restrict__ w,
        const float* __restrict__ beta_a,
        const float* __restrict__ beta_u,
        float inv_temp,
        float* __restrict__ out)
{
    extern __shared__ char smraw[];
    float4* sp4 = (float4*)smraw;                        // [28][32][5]
    float4* prm = (float4*)(smraw + 71680);              // [OO*8]
    float*  ss  = (float*)(smraw + 71680 + 1280);        // [32*12]
    float*  se  = ss + 32 * 12;                          // [32*12]
    float*  sa  = se + 32 * 12;                          // [28*32]
    float*  Ksm = sa + HWB * 32;                         // [OO]
    int*    swin = (int*)(Ksm + OO + 2);

    const int b   = blockIdx.y;
    const int ch  = blockIdx.x;
    const int hw0 = ch * HWB;
    const int tid = threadIdx.x;
    const int o   = tid >> 5;
    const int c   = tid & 31;

    // ---- prologue ---------------------------------------------------------
    {
        const float4* src4 = (const float4*)(pose + (size_t)(b * HW + hw0) * CC * 16);
        for (int idx = tid; idx < HWB * CC * 4; idx += TPB) {
            const int t_l = idx >> 7;
            const int rem = idx & 127;
            sp4[(t_l * 32 + (rem >> 2)) * 5 + (rem & 3)] = src4[idx];
        }
        const float* asrc = act + (size_t)(b * HW + hw0) * CC;
        for (int idx = tid; idx < HWB * CC; idx += TPB)
            sa[idx] = asrc[idx];
        if (tid < OO * 8) {
            const int po = tid >> 3, pk = tid & 7;
            const float* pp = g_params + (size_t)(b * OO + po) * 33;
            prm[po * 8 + pk] = make_float4(pp[1 + 2*pk], pp[2 + 2*pk],
                                           pp[17 + 2*pk], pp[18 + 2*pk]);
        }
        if (tid < OO) Ksm[tid] = g_params[(size_t)(b * OO + tid) * 33];
    }

    // per-thread w[c][o], rows packed as column pairs
    u64 wv[4][2];
    {
        const float4* wp = (const float4*)(w + (size_t)(c * OO + o) * 16);
        #pragma unroll
        for (int j = 0; j < 4; j++) {
            const float4 r = wp[j];
            wv[j][0] = pack2(r.x, r.y);
            wv[j][1] = pack2(r.z, r.w);
        }
    }

    float S0 = 0.f;
    u64 S1[8], S2[8];
    #pragma unroll
    for (int k = 0; k < 8; k++) { S1[k] = 0ull; S2[k] = 0ull; }

    __syncthreads();
    const float K = Ksm[o];

    for (int t = 0; t < HWB; t++) {
        const int hw   = hw0 + t;
        const int h    = hw / WWD;
        const int wpos = hw - h * WWD;

        // votes (held through softmax)
        const float4* row = sp4 + (t * 32 + c) * 5;
        u64 v[8];
        #pragma unroll
        for (int i = 0; i < 4; i++) {
            const float4 P = row[i];
            const u64 p0 = pdup(P.x), p1 = pdup(P.y), p2 = pdup(P.z), p3 = pdup(P.w);
            v[i*2+0] = fma2(p0, wv[0][0], fma2(p1, wv[1][0],
                       fma2(p2, wv[2][0], mul2(p3, wv[3][0]))));
            v[i*2+1] = fma2(p0, wv[0][1], fma2(p1, wv[1][1],
                       fma2(p2, wv[2][1], mul2(p3, wv[3][1]))));
        }
        v[1] = add2(v[1], pack2(0.f, (wpos + 0.5f) * (1.0f / WWD)));
        v[3] = add2(v[3], pack2(0.f, (h    + 0.5f) * (1.0f / HH)));

        // logit
        u64 e1 = 0ull, e2 = 0ull;
        #pragma unroll
        for (int k = 0; k < 8; k++) {
            const longlong2 q = *(const longlong2*)&prm[o * 8 + k];   // uniform
            e1 = fma2(mul2(v[k], v[k]), (u64)q.x, e1);
            e2 = fma2(v[k], (u64)q.y, e2);
        }
        float e1l, e1h, e2l, e2h;
        unpack2(e1, e1l, e1h);
        unpack2(e2, e2l, e2h);
        const float s = fmaf(-0.5f, e1l + e1h, K + e2l + e2h);

        ss[c * 12 + o] = s;
        __syncthreads();
        const float4 q0 = *(const float4*)(ss + c * 12);
        const float4 q1 = *(const float4*)(ss + c * 12 + 4);
        const float2 q2 = *(const float2*)(ss + c * 12 + 8);
        const float mx = fmaxf(fmaxf(fmaxf(fmaxf(q0.x, q0.y), fmaxf(q0.z, q0.w)),
                               fmaxf(fmaxf(q1.x, q1.y), fmaxf(q1.z, q1.w))),
                               fmaxf(q2.x, q2.y));
        const float e = __expf(s - mx);
        se[c * 12 + o] = e;
        __syncthreads();
        const float4 r0 = *(const float4*)(se + c * 12);
        const float4 r1 = *(const float4*)(se + c * 12 + 4);
        const float2 r2 = *(const float2*)(se + c * 12 + 8);
        const float den = (((r0.x + r0.y) + (r0.z + r0.w))
                         + ((r1.x + r1.y) + (r1.z + r1.w))) + (r2.x + r2.y);
        const float ap = sa[t * 32 + c] * __fdividef(e, den);

        S0 += ap;
        const u64 ap2 = pdup(ap);
        #pragma unroll
        for (int k = 0; k < 8; k++) {
            const u64 t1 = mul2(ap2, v[k]);
            S1[k] = add2(S1[k], t1);
            S2[k] = fma2(t1, v[k], S2[k]);
        }
    }

    // ---- reduce over 32 c's ----------------------------------------------
    #pragma unroll
    for (int off = 16; off > 0; off >>= 1) {
        S0 += __shfl_xor_sync(0xFFFFFFFFu, S0, off);
        #pragma unroll
        for (int k = 0; k < 8; k++) {
            u64 a1 = __shfl_xor_sync(0xFFFFFFFFu, S1[k], off);
            u64 a2 = __shfl_xor_sync(0xFFFFFFFFu, S2[k], off);
            S1[k] = add2(S1[k], a1);
            S2[k] = add2(S2[k], a2);
        }
    }
    if (c == 0) {
        float* dst = g_partials + (size_t)((b * NCH + ch) * OO + o) * 33;
        dst[0] = S0;
        #pragma unroll
        for (int k = 0; k < 8; k++) {
            float lo, hi;
            unpack2(S1[k], lo, hi);
            dst[1 + 2*k] = lo;  dst[2 + 2*k] = hi;
            unpack2(S2[k], lo, hi);
            dst[17 + 2*k] = lo; dst[18 + 2*k] = hi;
        }
    }

    // ---- winner block per batch does the reduce --------------------------
    __syncthreads();
    if (tid == 0) {
        __threadfence();
        int prev = atomicAdd(&g_count[b], 1);
        *swin = (prev == NCH - 1);
    }
    __syncthreads();
    if (!*swin) return;
    __threadfence();

    if (tid < OO * 16) {
        const int ro = tid >> 4;
        const int rd = tid & 15;

        float R0 = 0.f, R1 = 0.f, R2 = 0.f;
        #pragma unroll
        for (int g = 0; g < NCH; g++) {
            const float* p = g_partials + (size_t)((b * NCH + g) * OO + ro) * 33;
            R0 += p[0];
            R1 += p[1 + rd];
            R2 += p[17 + rd];
        }

        const float rs     = R0 + EPSF;
        const float inv_rs = 1.0f / rs;
        const float mu     = R1 * inv_rs;
        const float var    = fmaxf(R2 * inv_rs - mu * mu, 0.0f) + EPSF;
        const float lv     = __logf(var);
        const float ivar   = 1.0f / var;
        const float muinv  = mu * ivar;
        const float mive   = mu * muinv;

        float sumlv = lv, summive = mive;
        #pragma unroll
        for (int off = 1; off < 16; off <<= 1) {
            sumlv   += __shfl_xor_sync(0xFFFFFFFFu, sumlv,   off);
            summive += __shfl_xor_sync(0xFFFFFFFFu, summive, off);
        }

        const float cost = rs * (16.0f * beta_u[ro] + 0.5f * sumlv);
        const float x    = inv_temp * (beta_a[ro] - cost);
        const float actv = 1.0f / (1.0f + __expf(-x));

        if (FINAL) {
            out[(size_t)(b * OO + ro) * 16 + rd] = mu;
            if (rd == 0) out[BB * OO * 16 + b * OO + ro] = actv;
        } else {
            float* pp = g_params + (size_t)(b * OO + ro) * 33;
            pp[1 + rd]  = ivar;
            pp[17 + rd] = muinv;
            if (rd == 0)
                pp[0] = __logf(actv + EPSF)
                      - 0.5f * (16.0f * LOG2PI + sumlv)
                      - 0.5f * summive;
        }
    }
    if (tid == 0) g_count[b] = 0;
}

// ---------------------------------------------------------------------------
extern "C" void kernel_launch(void* const* d_in, const int* in_sizes, int n_in,
                              void* d_out, int out_size)
{
    const float* pose = (const float*)d_in[0];
    const float* act  = (const float*)d_in[1];
    const float* w    = (const float*)d_in[2];
    const float* ba   = (const float*)d_in[3];
    const float* bu   = (const float*)d_in[4];
    float* out = (float*)d_out;

    static int smem_set = 0;
    if (!smem_set) {   // driver state only; capture-safe
        cudaFuncSetAttribute(caps_em<0>, cudaFuncAttributeMaxDynamicSharedMemorySize, SMEM_EM);
        cudaFuncSetAttribute(caps_em<1>, cudaFuncAttributeMaxDynamicSharedMemorySize, SMEM_EM);
        smem_set = 1;
    }

    dim3 g0(ACH, BB);
    dim3 ga(NCH, BB);

    caps_mom<<<g0, 512>>>(pose, act, w, ba, bu);                          // it=0
    caps_em<0><<<ga, TPB, SMEM_EM>>>(pose, act, w, ba, bu, 2.0f, out);    // it=1
    caps_em<1><<<ga, TPB, SMEM_EM>>>(pose, act, w, ba, bu, 3.0f, out);    // it=2
}